// round 1
// baseline (speedup 1.0000x reference)
#include <cuda_runtime.h>
#include <cstdint>

// PoolingNms: MaxPool2d(k=3, stride=3) + MaxUnpool2d fused.
// x: [16, 1, 1536, 1536] fp32. Keep only the first-argmax element of each
// non-overlapping 3x3 block; zero everything else.
//
// Each thread processes 4 adjacent 3x3 blocks (a 3-row x 12-col patch),
// so all global traffic is aligned float4 (12 cols = 3 float4 per row).

static constexpr int W = 1536;
static constexpr int H = 1536;
static constexpr int BC = 16;            // batch * channels
static constexpr int WQ = W / 12;        // 128 patches per row-group
static constexpr int HK = H / 3;         // 512 row-groups
static constexpr int TOTAL = BC * HK * WQ;  // 1,048,576 threads

__global__ __launch_bounds__(256)
void pooling_nms_kernel(const float* __restrict__ x, float* __restrict__ out) {
    int idx = blockIdx.x * blockDim.x + threadIdx.x;
    if (idx >= TOTAL) return;

    int wq   = idx & (WQ - 1);       // 0..127
    int rest = idx >> 7;
    int hk   = rest & (HK - 1);      // 0..511
    int bc   = rest >> 9;            // 0..15

    size_t base = ((size_t)bc * H + (size_t)hk * 3) * W + (size_t)wq * 12;
    const float4* __restrict__ src = reinterpret_cast<const float4*>(x + base);
    float4* __restrict__ dst       = reinterpret_cast<float4*>(out + base);

    // Load 3 rows x 12 cols as 9 float4s.
    float v[3][12];
    const int row4 = W / 4;  // float4 stride per image row
    #pragma unroll
    for (int dr = 0; dr < 3; dr++) {
        #pragma unroll
        for (int q = 0; q < 3; q++) {
            float4 t = src[(size_t)dr * row4 + q];
            v[dr][q * 4 + 0] = t.x;
            v[dr][q * 4 + 1] = t.y;
            v[dr][q * 4 + 2] = t.z;
            v[dr][q * 4 + 3] = t.w;
        }
    }

    // For each of the 4 blocks: first-argmax (strict > keeps earliest index
    // in dr*3+dc order, matching jnp.argmax), then zero everything else.
    #pragma unroll
    for (int b = 0; b < 4; b++) {
        int c0 = b * 3;
        float best = v[0][c0];
        int bi = 0;
        #pragma unroll
        for (int i = 1; i < 9; i++) {
            float val = v[i / 3][c0 + (i % 3)];
            if (val > best) { best = val; bi = i; }
        }
        #pragma unroll
        for (int i = 0; i < 9; i++)
            v[i / 3][c0 + (i % 3)] = 0.0f;
        v[bi / 3][c0 + (bi % 3)] = best;
    }

    // Store 9 float4s.
    #pragma unroll
    for (int dr = 0; dr < 3; dr++) {
        #pragma unroll
        for (int q = 0; q < 3; q++) {
            float4 t;
            t.x = v[dr][q * 4 + 0];
            t.y = v[dr][q * 4 + 1];
            t.z = v[dr][q * 4 + 2];
            t.w = v[dr][q * 4 + 3];
            dst[(size_t)dr * row4 + q] = t;
        }
    }
}

extern "C" void kernel_launch(void* const* d_in, const int* in_sizes, int n_in,
                              void* d_out, int out_size) {
    const float* x = (const float*)d_in[0];
    float* out = (float*)d_out;
    const int threads = 256;
    const int blocks = TOTAL / threads;  // 4096
    pooling_nms_kernel<<<blocks, threads>>>(x, out);
}